// round 8
// baseline (speedup 1.0000x reference)
#include <cuda_runtime.h>
#include <cuda_bf16.h>
#include <math.h>
#include <stdint.h>

#define BATCH 2
#define SEQ   2048
#define DM    1024
#define NH    16
#define HD    64
#define MTOT  (BATCH*SEQ)   // 4096

typedef unsigned short ushort_t;

// ---------------- scratch (__device__ globals; no cudaMalloc allowed) -------
__device__ __nv_bfloat16 g_xh[(size_t)MTOT*DM];   // x  [M,K] hi/lo
__device__ __nv_bfloat16 g_xl[(size_t)MTOT*DM];
__device__ __nv_bfloat16 g_wqh[(size_t)DM*DM];    // W^T [N,K] hi/lo
__device__ __nv_bfloat16 g_wql[(size_t)DM*DM];
__device__ __nv_bfloat16 g_wkh[(size_t)DM*DM];
__device__ __nv_bfloat16 g_wkl[(size_t)DM*DM];
__device__ __nv_bfloat16 g_wvh[(size_t)DM*DM];
__device__ __nv_bfloat16 g_wvl[(size_t)DM*DM];
__device__ __nv_bfloat16 g_woh[(size_t)DM*DM];
__device__ __nv_bfloat16 g_wol[(size_t)DM*DM];
__device__ __nv_bfloat16 g_qh[(size_t)MTOT*DM];   // [B,H,S,64]
__device__ __nv_bfloat16 g_ql[(size_t)MTOT*DM];
__device__ __nv_bfloat16 g_kh[(size_t)MTOT*DM];
__device__ __nv_bfloat16 g_kl[(size_t)MTOT*DM];
__device__ __nv_bfloat16 g_vh[(size_t)MTOT*DM];
__device__ __nv_bfloat16 g_vl[(size_t)MTOT*DM];
__device__ __nv_bfloat16 g_oh[(size_t)MTOT*DM];   // attn out [B,S,D]
__device__ __nv_bfloat16 g_ol[(size_t)MTOT*DM];

// ---------------- helpers ---------------------------------------------------
__device__ __forceinline__ void splitpack(float x, float y,
                                          unsigned &hi, unsigned &lo) {
    __nv_bfloat16 hx = __float2bfloat16(x);
    __nv_bfloat16 hy = __float2bfloat16(y);
    float lx = x - __bfloat162float(hx);
    float ly = y - __bfloat162float(hy);
    hi = ((unsigned)__bfloat16_as_ushort(hy) << 16) |
          (unsigned)__bfloat16_as_ushort(hx);
    lo = ((unsigned)__bfloat16_as_ushort(__float2bfloat16(ly)) << 16) |
          (unsigned)__bfloat16_as_ushort(__float2bfloat16(lx));
}
__device__ __forceinline__ void ldsm4(unsigned* r, const void* p) {
    unsigned a = (unsigned)__cvta_generic_to_shared(p);
    asm volatile("ldmatrix.sync.aligned.m8n8.x4.shared.b16 {%0,%1,%2,%3}, [%4];"
                 : "=r"(r[0]), "=r"(r[1]), "=r"(r[2]), "=r"(r[3]) : "r"(a));
}
__device__ __forceinline__ void ldsm4t(unsigned* r, const void* p) {
    unsigned a = (unsigned)__cvta_generic_to_shared(p);
    asm volatile("ldmatrix.sync.aligned.m8n8.x4.trans.shared.b16 {%0,%1,%2,%3}, [%4];"
                 : "=r"(r[0]), "=r"(r[1]), "=r"(r[2]), "=r"(r[3]) : "r"(a));
}
__device__ __forceinline__ void mma16816(float* c, const unsigned* a,
                                         const unsigned* b) {
    asm volatile(
        "mma.sync.aligned.m16n8k16.row.col.f32.bf16.bf16.f32 "
        "{%0,%1,%2,%3},{%4,%5,%6,%7},{%8,%9},{%0,%1,%2,%3};"
        : "+f"(c[0]), "+f"(c[1]), "+f"(c[2]), "+f"(c[3])
        : "r"(a[0]), "r"(a[1]), "r"(a[2]), "r"(a[3]), "r"(b[0]), "r"(b[1]));
}
__device__ __forceinline__ void cpa16(void* dst, const void* src) {
    unsigned d = (unsigned)__cvta_generic_to_shared(dst);
    asm volatile("cp.async.cg.shared.global [%0], [%1], 16;" :: "r"(d), "l"(src));
}
__device__ __forceinline__ void cpa_commit() {
    asm volatile("cp.async.commit_group;");
}
template <int N> __device__ __forceinline__ void cpa_wait() {
    asm volatile("cp.async.wait_group %0;" :: "n"(N));
}

// ============================================================================
// prep kernels
// ============================================================================
__global__ void split_kernel(const float2* __restrict__ src,
                             unsigned* __restrict__ hi,
                             unsigned* __restrict__ lo, int n2)
{
    for (int i = blockIdx.x * blockDim.x + threadIdx.x; i < n2;
         i += gridDim.x * blockDim.x) {
        float2 v = src[i];
        unsigned h, l;
        splitpack(v.x, v.y, h, l);
        hi[i] = h;
        lo[i] = l;
    }
}

// transpose + split: T[n,k] = W[k,n], hi/lo bf16 planes
__global__ void tsplit_kernel(const float* __restrict__ W,
                              __nv_bfloat16* __restrict__ Th,
                              __nv_bfloat16* __restrict__ Tl)
{
    __shared__ float t[32][33];
    const int n0 = blockIdx.x * 32, k0 = blockIdx.y * 32;
    const int tx = threadIdx.x, ty = threadIdx.y;
    #pragma unroll
    for (int i = 0; i < 4; i++)
        t[ty + 8 * i][tx] = W[(size_t)(k0 + ty + 8 * i) * DM + n0 + tx];
    __syncthreads();
    #pragma unroll
    for (int i = 0; i < 4; i++) {
        const float v = t[tx][ty + 8 * i];       // = W[k0+tx][n0+ty+8i]
        const __nv_bfloat16 h = __float2bfloat16(v);
        const size_t idx = (size_t)(n0 + ty + 8 * i) * DM + k0 + tx;
        Th[idx] = h;
        Tl[idx] = __float2bfloat16(v - __bfloat162float(h));
    }
}

// ============================================================================
// Split-bf16 GEMM v2: C[M,N] = A[M,K] @ B^T + bias, B stored [N,K] K-major.
// Tile 128x128x32, 128 threads (4 warps 2x2), warp tile 64x64 (mi=4, nq=4).
// 16 ldsm4 feed 96 HMMA per k-slice -> tensor-bound.
// MODE 0: fp32 row-major out. MODE 1: bf16 hi/lo [B,H,S,64] out, scaled.
// ============================================================================
#define KC  32
#define PST 40                 // padded stride, halves (80 B)
#define PL  (128*PST)          // plane: 5120 halves
#define STG (4*PL)             // Ah,Al,Bh,Bl per stage
#define GEMM_SMEM (2*STG*2)    // 81920 bytes

template <int MODE>
__global__ void __launch_bounds__(128, 2) mma_gemm(
    const __nv_bfloat16* __restrict__ Ah, const __nv_bfloat16* __restrict__ Al,
    const __nv_bfloat16* __restrict__ Bh, const __nv_bfloat16* __restrict__ Bl,
    const float* __restrict__ bias, float scale,
    float* __restrict__ Cf,
    __nv_bfloat16* __restrict__ Chi, __nv_bfloat16* __restrict__ Clo)
{
    extern __shared__ ushort_t gsm[];

    const int tid  = threadIdx.x;
    const int lane = tid & 31, warp = tid >> 5;        // 4 warps
    const int wm = (warp >> 1) * 64, wn = (warp & 1) * 64;
    const int brow = blockIdx.y * 128, bcol = blockIdx.x * 128;

    const __nv_bfloat16* planes[4] = { Ah, Al, Bh, Bl };

    // 2048 cpa16 per stage, 16 per thread
    auto load_stage = [&](int s, int kt) {
        #pragma unroll
        for (int it = 0; it < 16; it++) {
            const int idx = tid + it * 128;
            const int p = idx >> 9;           // plane 0..3
            const int r = (idx >> 2) & 127;   // row
            const int c = idx & 3;            // 8-half column group
            const int grow = (p < 2 ? brow : bcol) + r;
            cpa16(&gsm[s * STG + p * PL + r * PST + c * 8],
                  planes[p] + (size_t)grow * DM + kt + c * 8);
        }
    };

    float acc[4][8][4];
    #pragma unroll
    for (int i = 0; i < 4; i++)
        #pragma unroll
        for (int j = 0; j < 8; j++)
            #pragma unroll
            for (int c = 0; c < 4; c++) acc[i][j][c] = 0.f;

    load_stage(0, 0);  cpa_commit();
    load_stage(1, KC); cpa_commit();

    const int NIT = DM / KC;   // 32
    for (int it = 0; it < NIT; it++) {
        if (it < NIT - 1) cpa_wait<1>(); else cpa_wait<0>();
        __syncthreads();

        const int s = it & 1;
        ushort_t* A0 = gsm + s * STG;
        ushort_t* A1 = A0 + PL;
        ushort_t* B0 = A1 + PL;
        ushort_t* B1 = B0 + PL;

        #pragma unroll
        for (int ks = 0; ks < 2; ks++) {
            unsigned ah[4][4], al[4][4];
            const int ac = ks * 16 + ((lane & 16) ? 8 : 0);
            #pragma unroll
            for (int mi = 0; mi < 4; mi++) {
                const int ar = wm + 16 * mi + (lane & 15);
                ldsm4(ah[mi], &A0[ar * PST + ac]);
                ldsm4(al[mi], &A1[ar * PST + ac]);
            }
            #pragma unroll
            for (int nq = 0; nq < 4; nq++) {
                // verified non-trans B convention ([N,K] rows): n on lane&16, k on lane&8
                const int br = wn + nq * 16 + (lane & 7) + ((lane & 16) ? 8 : 0);
                const int bc = ks * 16 + ((lane & 8) ? 8 : 0);
                unsigned bh[4], bl[4];
                ldsm4(bh, &B0[br * PST + bc]);
                ldsm4(bl, &B1[br * PST + bc]);
                #pragma unroll
                for (int mi = 0; mi < 4; mi++) {
                    mma16816(acc[mi][2 * nq],     ah[mi], bh + 0);
                    mma16816(acc[mi][2 * nq + 1], ah[mi], bh + 2);
                    mma16816(acc[mi][2 * nq],     ah[mi], bl + 0);
                    mma16816(acc[mi][2 * nq + 1], ah[mi], bl + 2);
                    mma16816(acc[mi][2 * nq],     al[mi], bh + 0);
                    mma16816(acc[mi][2 * nq + 1], al[mi], bh + 2);
                }
            }
        }
        __syncthreads();
        if (it + 2 < NIT) { load_stage(s, (it + 2) * KC); cpa_commit(); }
    }

    const int g = lane >> 2, tg = lane & 3;
    #pragma unroll
    for (int mi = 0; mi < 4; mi++) {
        #pragma unroll
        for (int nf = 0; nf < 8; nf++) {
            const int col = bcol + wn + nf * 8 + 2 * tg;
            const float b0 = bias[col], b1 = bias[col + 1];
            #pragma unroll
            for (int half = 0; half < 2; half++) {
                const int row = brow + wm + 16 * mi + g + 8 * half;
                const float v0 = (acc[mi][nf][2 * half + 0] + b0) * scale;
                const float v1 = (acc[mi][nf][2 * half + 1] + b1) * scale;
                if (MODE == 0) {
                    *(float2*)(Cf + (size_t)row * DM + col) = make_float2(v0, v1);
                } else {
                    const int bb = row >> 11, sq = row & (SEQ - 1);
                    const int hh = col >> 6,  dd = col & (HD - 1);
                    const size_t idx = (((size_t)(bb * NH + hh) * SEQ + sq) * HD + dd);
                    unsigned hi, lo;
                    splitpack(v0, v1, hi, lo);
                    *(unsigned*)(Chi + idx) = hi;
                    *(unsigned*)(Clo + idx) = lo;
                }
            }
        }
    }
}

// ============================================================================
// Flash attention (UNCHANGED from round-5 passing version)
// ============================================================================
#define QST 72
#define Q_PL   (128*QST)
#define KV_PL  (64*QST)
#define KV_STG (4*KV_PL)
#define KV_BASE (2*Q_PL)
#define ATTN_SMEM ((2*Q_PL + 2*KV_STG)*2)   // 110592 bytes

__global__ void __launch_bounds__(128, 2) mma_attn(
    const __nv_bfloat16* __restrict__ Qh, const __nv_bfloat16* __restrict__ Ql,
    const __nv_bfloat16* __restrict__ Kh, const __nv_bfloat16* __restrict__ Kl,
    const __nv_bfloat16* __restrict__ Vh, const __nv_bfloat16* __restrict__ Vl,
    __nv_bfloat16* __restrict__ Ohi, __nv_bfloat16* __restrict__ Olo)
{
    extern __shared__ ushort_t sm[];

    const int tid = threadIdx.x, lane = tid & 31, warp = tid >> 5;
    const int q0 = blockIdx.x * 128;
    const int h  = blockIdx.y,  b = blockIdx.z;
    const size_t hoff = (size_t)(b * NH + h) * SEQ * HD;

    const __nv_bfloat16* kvp[4] = { Kh + hoff, Kl + hoff, Vh + hoff, Vl + hoff };

    const int lr = tid >> 3, lc = (tid & 7) * 8;

    auto load_kv = [&](int stage, int kv0) {
        #pragma unroll
        for (int k = 0; k < 16; k++) {
            const int p   = k >> 2;
            const int row = lr + (k & 3) * 16;
            cpa16(&sm[KV_BASE + stage * KV_STG + p * KV_PL + row * QST + lc],
                  kvp[p] + (size_t)(kv0 + row) * HD + lc);
        }
    };

    {
        const __nv_bfloat16* qp[2] = { Qh + hoff, Ql + hoff };
        #pragma unroll
        for (int k = 0; k < 16; k++) {
            const int p   = k >> 3;
            const int row = lr + (k & 7) * 16;
            cpa16(&sm[p * Q_PL + row * QST + lc],
                  qp[p] + (size_t)(q0 + row) * HD + lc);
        }
    }
    load_kv(0, 0); cpa_commit();
    load_kv(1, 64); cpa_commit();

    const int g = lane >> 2, tg = lane & 3;
    float m[2][2], l[2][2], o[2][8][4];
    #pragma unroll
    for (int mi = 0; mi < 2; mi++) {
        m[mi][0] = -INFINITY; m[mi][1] = -INFINITY;
        l[mi][0] = 0.f;       l[mi][1] = 0.f;
        #pragma unroll
        for (int i = 0; i < 8; i++)
            #pragma unroll
            for (int c = 0; c < 4; c++) o[mi][i][c] = 0.f;
    }

    const int NIT = SEQ / 64;   // 32
    for (int it = 0; it < NIT; it++) {
        if (it < NIT - 1) cpa_wait<1>(); else cpa_wait<0>();
        __syncthreads();

        const int stage = it & 1;
        ushort_t* Ksh = sm + KV_BASE + stage * KV_STG;
        ushort_t* Ksl = Ksh + KV_PL;
        ushort_t* Vsh = Ksl + KV_PL;
        ushort_t* Vsl = Vsh + KV_PL;

        float s[2][8][4];
        #pragma unroll
        for (int mi = 0; mi < 2; mi++)
            #pragma unroll
            for (int i = 0; i < 8; i++)
                #pragma unroll
                for (int c = 0; c < 4; c++) s[mi][i][c] = 0.f;

        #pragma unroll
        for (int ks = 0; ks < 4; ks++) {
            unsigned ah[2][4], al[2][4];
            #pragma unroll
            for (int mi = 0; mi < 2; mi++) {
                const int ar = warp * 32 + 16 * mi + (lane & 15);
                const int ac = ks * 16 + ((lane & 16) ? 8 : 0);
                ldsm4(ah[mi], &sm[0 * Q_PL + ar * QST + ac]);
                ldsm4(al[mi], &sm[1 * Q_PL + ar * QST + ac]);
            }
            #pragma unroll
            for (int nq = 0; nq < 4; nq++) {
                const int srow = nq * 16 + (lane & 7) + ((lane & 16) ? 8 : 0);
                const int dcol = ks * 16 + ((lane & 8) ? 8 : 0);
                unsigned bh[4], bl[4];
                ldsm4(bh, &Ksh[srow * QST + dcol]);
                ldsm4(bl, &Ksl[srow * QST + dcol]);
                #pragma unroll
                for (int mi = 0; mi < 2; mi++) {
                    mma16816(s[mi][2 * nq],     ah[mi], bh + 0);
                    mma16816(s[mi][2 * nq + 1], ah[mi], bh + 2);
                    mma16816(s[mi][2 * nq],     ah[mi], bl + 0);
                    mma16816(s[mi][2 * nq + 1], ah[mi], bl + 2);
                    mma16816(s[mi][2 * nq],     al[mi], bh + 0);
                    mma16816(s[mi][2 * nq + 1], al[mi], bh + 2);
                }
            }
        }

        unsigned ph[2][8][2], pl[2][8][2];
        #pragma unroll
        for (int mi = 0; mi < 2; mi++) {
            float mx0 = -INFINITY, mx1 = -INFINITY;
            #pragma unroll
            for (int i = 0; i < 8; i++) {
                mx0 = fmaxf(mx0, fmaxf(s[mi][i][0], s[mi][i][1]));
                mx1 = fmaxf(mx1, fmaxf(s[mi][i][2], s[mi][i][3]));
            }
            mx0 = fmaxf(mx0, __shfl_xor_sync(0xffffffffu, mx0, 1));
            mx0 = fmaxf(mx0, __shfl_xor_sync(0xffffffffu, mx0, 2));
            mx1 = fmaxf(mx1, __shfl_xor_sync(0xffffffffu, mx1, 1));
            mx1 = fmaxf(mx1, __shfl_xor_sync(0xffffffffu, mx1, 2));
            const float mn0 = fmaxf(m[mi][0], mx0), mn1 = fmaxf(m[mi][1], mx1);
            const float c0 = __expf(m[mi][0] - mn0), c1 = __expf(m[mi][1] - mn1);
            m[mi][0] = mn0; m[mi][1] = mn1;
            float rs0 = 0.f, rs1 = 0.f;
            #pragma unroll
            for (int i = 0; i < 8; i++) {
                s[mi][i][0] = __expf(s[mi][i][0] - mn0);
                s[mi][i][1] = __expf(s[mi][i][1] - mn0);
                s[mi][i][2] = __expf(s[mi][i][2] - mn1);
                s[mi][i][3] = __expf(s[mi][i][3] - mn1);
                rs0 += s[mi][i][0] + s[mi][i][1];
                rs1 += s[mi][i][2] + s[mi][i][3];
            }
            rs0 += __shfl_xor_sync(0xffffffffu, rs0, 1);
            rs0 += __shfl_xor_sync(0xffffffffu, rs0, 2);
            rs1 += __shfl_xor_sync(0xffffffffu, rs1, 1);
            rs1 += __shfl_xor_sync(0xffffffffu, rs1, 2);
            l[mi][0] = l[mi][0] * c0 + rs0;
            l[mi][1] = l[mi][1] * c1 + rs1;
            #pragma unroll
            for (int i = 0; i < 8; i++) {
                o[mi][i][0] *= c0; o[mi][i][1] *= c0;
                o[mi][i][2] *= c1; o[mi][i][3] *= c1;
                splitpack(s[mi][i][0], s[mi][i][1], ph[mi][i][0], pl[mi][i][0]);
                splitpack(s[mi][i][2], s[mi][i][3], ph[mi][i][1], pl[mi][i][1]);
            }
        }

        #pragma unroll
        for (int kss = 0; kss < 4; kss++) {
            unsigned a2h[2][4], a2l[2][4];
            #pragma unroll
            for (int mi = 0; mi < 2; mi++) {
                a2h[mi][0] = ph[mi][2 * kss][0];     a2h[mi][1] = ph[mi][2 * kss][1];
                a2h[mi][2] = ph[mi][2 * kss + 1][0]; a2h[mi][3] = ph[mi][2 * kss + 1][1];
                a2l[mi][0] = pl[mi][2 * kss][0];     a2l[mi][1] = pl[mi][2 * kss][1];
                a2l[mi][2] = pl[mi][2 * kss + 1][0]; a2l[mi][3] = pl[mi][2 * kss + 1][1];
            }
            #pragma unroll
            for (int nq = 0; nq < 4; nq++) {
                const int srow = kss * 16 + (lane & 7) + ((lane & 8) ? 8 : 0);
                const int dcol = nq * 16 + ((lane & 16) ? 8 : 0);
                unsigned bh[4], bl[4];
                ldsm4t(bh, &Vsh[srow * QST + dcol]);
                ldsm4t(bl, &Vsl[srow * QST + dcol]);
                #pragma unroll
                for (int mi = 0; mi < 2; mi++) {
                    mma16816(o[mi][2 * nq],     a2h[mi], bh + 0);
                    mma16816(o[mi][2 * nq + 1], a2h[mi], bh + 2);
                    mma16816(o[mi][2 * nq],     a2h[mi], bl + 0);
                    mma16816(o[mi][2 * nq + 1], a2h[mi], bl + 2);
                    mma16816(o[mi][2 * nq],     a2l[mi], bh + 0);
                    mma16816(o[mi][2 * nq + 1], a2l[mi], bh + 2);
                }
            }
        }
        __syncthreads();
        if (it + 2 < NIT) { load_kv(stage, (it + 2) * 64); cpa_commit(); }
    }

    #pragma unroll
    for (int mi = 0; mi < 2; mi++) {
        const float i0 = 1.f / l[mi][0], i1 = 1.f / l[mi][1];
        #pragma unroll
        for (int nf = 0; nf < 8; nf++) {
            const int d  = h * HD + nf * 8 + 2 * tg;
            const int r0 = q0 + warp * 32 + 16 * mi + g;
            unsigned hi, lo;
            splitpack(o[mi][nf][0] * i0, o[mi][nf][1] * i0, hi, lo);
            *(unsigned*)(Ohi + (size_t)(b * SEQ + r0) * DM + d) = hi;
            *(unsigned*)(Olo + (size_t)(b * SEQ + r0) * DM + d) = lo;
            splitpack(o[mi][nf][2] * i1, o[mi][nf][3] * i1, hi, lo);
            *(unsigned*)(Ohi + (size_t)(b * SEQ + r0 + 8) * DM + d) = hi;
            *(unsigned*)(Olo + (size_t)(b * SEQ + r0 + 8) * DM + d) = lo;
        }
    }
}

// ============================================================================
// launch
// ============================================================================
extern "C" void kernel_launch(void* const* d_in, const int* in_sizes, int n_in,
                              void* d_out, int out_size)
{
    const float* x  = (const float*)d_in[0];
    const float* Wq = (const float*)d_in[1];
    const float* bq = (const float*)d_in[2];
    const float* Wk = (const float*)d_in[3];
    const float* bk = (const float*)d_in[4];
    const float* Wv = (const float*)d_in[5];
    const float* bv = (const float*)d_in[6];
    const float* Wo = (const float*)d_in[7];
    const float* bo = (const float*)d_in[8];
    float* out = (float*)d_out;

    void *xh, *xl, *wqh, *wql, *wkh, *wkl, *wvh, *wvl, *woh, *wol;
    void *qh, *ql, *kh, *kl, *vh, *vl, *oh, *ol;
    cudaGetSymbolAddress(&xh, g_xh);   cudaGetSymbolAddress(&xl, g_xl);
    cudaGetSymbolAddress(&wqh, g_wqh); cudaGetSymbolAddress(&wql, g_wql);
    cudaGetSymbolAddress(&wkh, g_wkh); cudaGetSymbolAddress(&wkl, g_wkl);
    cudaGetSymbolAddress(&wvh, g_wvh); cudaGetSymbolAddress(&wvl, g_wvl);
    cudaGetSymbolAddress(&woh, g_woh); cudaGetSymbolAddress(&wol, g_wol);
    cudaGetSymbolAddress(&qh, g_qh);   cudaGetSymbolAddress(&ql, g_ql);
    cudaGetSymbolAddress(&kh, g_kh);   cudaGetSymbolAddress(&kl, g_kl);
    cudaGetSymbolAddress(&vh, g_vh);   cudaGetSymbolAddress(&vl, g_vl);
    cudaGetSymbolAddress(&oh, g_oh);   cudaGetSymbolAddress(&ol, g_ol);

    // prep: split x (row-major) + transpose-split the four weights to [N,K]
    split_kernel<<<512, 256>>>((const float2*)x, (unsigned*)xh, (unsigned*)xl, MTOT*DM/2);
    dim3 tb(32, 8), tg2(DM / 32, DM / 32);
    tsplit_kernel<<<tg2, tb>>>(Wq, (__nv_bfloat16*)wqh, (__nv_bfloat16*)wql);
    tsplit_kernel<<<tg2, tb>>>(Wk, (__nv_bfloat16*)wkh, (__nv_bfloat16*)wkl);
    tsplit_kernel<<<tg2, tb>>>(Wv, (__nv_bfloat16*)wvh, (__nv_bfloat16*)wvl);
    tsplit_kernel<<<tg2, tb>>>(Wo, (__nv_bfloat16*)woh, (__nv_bfloat16*)wol);

    cudaFuncSetAttribute(mma_gemm<0>, cudaFuncAttributeMaxDynamicSharedMemorySize, GEMM_SMEM);
    cudaFuncSetAttribute(mma_gemm<1>, cudaFuncAttributeMaxDynamicSharedMemorySize, GEMM_SMEM);
    cudaFuncSetAttribute(mma_attn, cudaFuncAttributeMaxDynamicSharedMemorySize, ATTN_SMEM);

    dim3 gg(DM / 128, MTOT / 128);   // (8, 32)
    mma_gemm<1><<<gg, 128, GEMM_SMEM>>>(
        (const __nv_bfloat16*)xh, (const __nv_bfloat16*)xl,
        (const __nv_bfloat16*)wqh, (const __nv_bfloat16*)wql,
        bq, 0.125f, nullptr, (__nv_bfloat16*)qh, (__nv_bfloat16*)ql);
    mma_gemm<1><<<gg, 128, GEMM_SMEM>>>(
        (const __nv_bfloat16*)xh, (const __nv_bfloat16*)xl,
        (const __nv_bfloat16*)wkh, (const __nv_bfloat16*)wkl,
        bk, 1.f, nullptr, (__nv_bfloat16*)kh, (__nv_bfloat16*)kl);
    mma_gemm<1><<<gg, 128, GEMM_SMEM>>>(
        (const __nv_bfloat16*)xh, (const __nv_bfloat16*)xl,
        (const __nv_bfloat16*)wvh, (const __nv_bfloat16*)wvl,
        bv, 1.f, nullptr, (__nv_bfloat16*)vh, (__nv_bfloat16*)vl);

    mma_attn<<<dim3(SEQ / 128, NH, BATCH), 128, ATTN_SMEM>>>(
        (const __nv_bfloat16*)qh, (const __nv_bfloat16*)ql,
        (const __nv_bfloat16*)kh, (const __nv_bfloat16*)kl,
        (const __nv_bfloat16*)vh, (const __nv_bfloat16*)vl,
        (__nv_bfloat16*)oh, (__nv_bfloat16*)ol);

    mma_gemm<0><<<gg, 128, GEMM_SMEM>>>(
        (const __nv_bfloat16*)oh, (const __nv_bfloat16*)ol,
        (const __nv_bfloat16*)woh, (const __nv_bfloat16*)wol,
        bo, 1.f, out, nullptr, nullptr);
}

// round 11
// speedup vs baseline: 1.5422x; 1.5422x over previous
#include <cuda_runtime.h>
#include <cuda_bf16.h>
#include <math.h>
#include <stdint.h>

#define BATCH 2
#define SEQ   2048
#define DM    1024
#define NH    16
#define HD    64
#define MTOT  (BATCH*SEQ)   // 4096

typedef unsigned short ushort_t;

// ---------------- scratch (__device__ globals; no cudaMalloc allowed) -------
__device__ __nv_bfloat16 g_xh[(size_t)MTOT*DM];   // x  [M,K] hi/lo
__device__ __nv_bfloat16 g_xl[(size_t)MTOT*DM];
__device__ __nv_bfloat16 g_wqh[(size_t)DM*DM];    // W^T [N,K] hi/lo
__device__ __nv_bfloat16 g_wql[(size_t)DM*DM];
__device__ __nv_bfloat16 g_wkh[(size_t)DM*DM];
__device__ __nv_bfloat16 g_wkl[(size_t)DM*DM];
__device__ __nv_bfloat16 g_wvh[(size_t)DM*DM];
__device__ __nv_bfloat16 g_wvl[(size_t)DM*DM];
__device__ __nv_bfloat16 g_woh[(size_t)DM*DM];
__device__ __nv_bfloat16 g_wol[(size_t)DM*DM];
__device__ __nv_bfloat16 g_qh[(size_t)MTOT*DM];   // [B,H,S,64]
__device__ __nv_bfloat16 g_ql[(size_t)MTOT*DM];
__device__ __nv_bfloat16 g_kh[(size_t)MTOT*DM];
__device__ __nv_bfloat16 g_kl[(size_t)MTOT*DM];
__device__ __nv_bfloat16 g_vh[(size_t)MTOT*DM];
__device__ __nv_bfloat16 g_vl[(size_t)MTOT*DM];
__device__ __nv_bfloat16 g_oh[(size_t)MTOT*DM];   // attn out [B,S,D]
__device__ __nv_bfloat16 g_ol[(size_t)MTOT*DM];

// ---------------- helpers ---------------------------------------------------
__device__ __forceinline__ void splitpack(float x, float y,
                                          unsigned &hi, unsigned &lo) {
    __nv_bfloat16 hx = __float2bfloat16(x);
    __nv_bfloat16 hy = __float2bfloat16(y);
    float lx = x - __bfloat162float(hx);
    float ly = y - __bfloat162float(hy);
    hi = ((unsigned)__bfloat16_as_ushort(hy) << 16) |
          (unsigned)__bfloat16_as_ushort(hx);
    lo = ((unsigned)__bfloat16_as_ushort(__float2bfloat16(ly)) << 16) |
          (unsigned)__bfloat16_as_ushort(__float2bfloat16(lx));
}
__device__ __forceinline__ void ldsm4(unsigned* r, const void* p) {
    unsigned a = (unsigned)__cvta_generic_to_shared(p);
    asm volatile("ldmatrix.sync.aligned.m8n8.x4.shared.b16 {%0,%1,%2,%3}, [%4];"
                 : "=r"(r[0]), "=r"(r[1]), "=r"(r[2]), "=r"(r[3]) : "r"(a));
}
__device__ __forceinline__ void ldsm4t(unsigned* r, const void* p) {
    unsigned a = (unsigned)__cvta_generic_to_shared(p);
    asm volatile("ldmatrix.sync.aligned.m8n8.x4.trans.shared.b16 {%0,%1,%2,%3}, [%4];"
                 : "=r"(r[0]), "=r"(r[1]), "=r"(r[2]), "=r"(r[3]) : "r"(a));
}
__device__ __forceinline__ void mma16816(float* c, const unsigned* a,
                                         const unsigned* b) {
    asm volatile(
        "mma.sync.aligned.m16n8k16.row.col.f32.bf16.bf16.f32 "
        "{%0,%1,%2,%3},{%4,%5,%6,%7},{%8,%9},{%0,%1,%2,%3};"
        : "+f"(c[0]), "+f"(c[1]), "+f"(c[2]), "+f"(c[3])
        : "r"(a[0]), "r"(a[1]), "r"(a[2]), "r"(a[3]), "r"(b[0]), "r"(b[1]));
}
__device__ __forceinline__ void cpa16(void* dst, const void* src) {
    unsigned d = (unsigned)__cvta_generic_to_shared(dst);
    asm volatile("cp.async.cg.shared.global [%0], [%1], 16;" :: "r"(d), "l"(src));
}
__device__ __forceinline__ void cpa_commit() {
    asm volatile("cp.async.commit_group;");
}
template <int N> __device__ __forceinline__ void cpa_wait() {
    asm volatile("cp.async.wait_group %0;" :: "n"(N));
}

// ============================================================================
// prep kernels
// ============================================================================
__global__ void split_kernel(const float2* __restrict__ src,
                             unsigned* __restrict__ hi,
                             unsigned* __restrict__ lo, int n2)
{
    for (int i = blockIdx.x * blockDim.x + threadIdx.x; i < n2;
         i += gridDim.x * blockDim.x) {
        float2 v = src[i];
        unsigned h, l;
        splitpack(v.x, v.y, h, l);
        hi[i] = h;
        lo[i] = l;
    }
}

// transpose + split: T[n,k] = W[k,n], hi/lo bf16 planes
__global__ void tsplit_kernel(const float* __restrict__ W,
                              __nv_bfloat16* __restrict__ Th,
                              __nv_bfloat16* __restrict__ Tl)
{
    __shared__ float t[32][33];
    const int n0 = blockIdx.x * 32, k0 = blockIdx.y * 32;
    const int tx = threadIdx.x, ty = threadIdx.y;
    #pragma unroll
    for (int i = 0; i < 4; i++)
        t[ty + 8 * i][tx] = W[(size_t)(k0 + ty + 8 * i) * DM + n0 + tx];
    __syncthreads();
    #pragma unroll
    for (int i = 0; i < 4; i++) {
        const float v = t[tx][ty + 8 * i];       // = W[k0+tx][n0+ty+8i]
        const __nv_bfloat16 h = __float2bfloat16(v);
        const size_t idx = (size_t)(n0 + ty + 8 * i) * DM + k0 + tx;
        Th[idx] = h;
        Tl[idx] = __float2bfloat16(v - __bfloat162float(h));
    }
}

// ============================================================================
// Split-bf16 GEMM v3: C[M,N] = A[M,K] @ B^T + bias, B stored [N,K] K-major.
// Tile 128x128x32, 256 thr, 8 warps (4m x 2n), warp 32x64 (round-5 shape).
// NEW: per k-slice, load ALL fragments, then issue MMAs grouped by split
// term (16x hh, 16x hl, 16x lh) -> same-acc dependency distance 16.
// MODE 0: fp32 row-major out. MODE 1: bf16 hi/lo [B,H,S,64] out, scaled.
// ============================================================================
#define KC  32
#define PST 40                 // padded stride, halves (80 B)
#define PL  (128*PST)          // plane: 5120 halves
#define STG (4*PL)             // Ah,Al,Bh,Bl per stage
#define GEMM_SMEM (2*STG*2)    // 81920 bytes

template <int MODE>
__global__ void __launch_bounds__(256, 2) mma_gemm(
    const __nv_bfloat16* __restrict__ Ah, const __nv_bfloat16* __restrict__ Al,
    const __nv_bfloat16* __restrict__ Bh, const __nv_bfloat16* __restrict__ Bl,
    const float* __restrict__ bias, float scale,
    float* __restrict__ Cf,
    __nv_bfloat16* __restrict__ Chi, __nv_bfloat16* __restrict__ Clo)
{
    extern __shared__ ushort_t gsm[];

    const int tid  = threadIdx.x;
    const int lane = tid & 31, warp = tid >> 5;        // 8 warps
    const int wm = (warp >> 1) * 32, wn = (warp & 1) * 64;
    const int brow = blockIdx.y * 128, bcol = blockIdx.x * 128;

    const __nv_bfloat16* planes[4] = { Ah, Al, Bh, Bl };

    // 2048 cpa16 per stage, 8 per thread
    auto load_stage = [&](int s, int kt) {
        #pragma unroll
        for (int it = 0; it < 8; it++) {
            const int idx = tid + it * 256;
            const int p = idx >> 9;           // plane 0..3 (512 each)
            const int r = (idx >> 2) & 127;   // row
            const int c = idx & 3;            // 8-half column group
            const int grow = (p < 2 ? brow : bcol) + r;
            cpa16(&gsm[s * STG + p * PL + r * PST + c * 8],
                  planes[p] + (size_t)grow * DM + kt + c * 8);
        }
    };

    float acc[2][8][4];
    #pragma unroll
    for (int i = 0; i < 2; i++)
        #pragma unroll
        for (int j = 0; j < 8; j++)
            #pragma unroll
            for (int c = 0; c < 4; c++) acc[i][j][c] = 0.f;

    load_stage(0, 0);  cpa_commit();
    load_stage(1, KC); cpa_commit();

    const int NIT = DM / KC;   // 32
    for (int it = 0; it < NIT; it++) {
        if (it < NIT - 1) cpa_wait<1>(); else cpa_wait<0>();
        __syncthreads();

        const int s = it & 1;
        ushort_t* A0 = gsm + s * STG;
        ushort_t* A1 = A0 + PL;
        ushort_t* B0 = A1 + PL;
        ushort_t* B1 = B0 + PL;

        #pragma unroll
        for (int ks = 0; ks < 2; ks++) {
            // ---- load ALL fragments for this k-slice (12 ldsm4) ----
            unsigned ah[2][4], al[2][4], bh[4][4], bl[4][4];
            const int ac = ks * 16 + ((lane & 16) ? 8 : 0);
            #pragma unroll
            for (int mi = 0; mi < 2; mi++) {
                const int ar = wm + 16 * mi + (lane & 15);
                ldsm4(ah[mi], &A0[ar * PST + ac]);
                ldsm4(al[mi], &A1[ar * PST + ac]);
            }
            const int bc = ks * 16 + ((lane & 8) ? 8 : 0);
            #pragma unroll
            for (int nq = 0; nq < 4; nq++) {
                const int br = wn + nq * 16 + (lane & 7) + ((lane & 16) ? 8 : 0);
                ldsm4(bh[nq], &B0[br * PST + bc]);
                ldsm4(bl[nq], &B1[br * PST + bc]);
            }
            // ---- term hh: 16 MMAs, every acc touched once ----
            #pragma unroll
            for (int nq = 0; nq < 4; nq++)
                #pragma unroll
                for (int mi = 0; mi < 2; mi++) {
                    mma16816(acc[mi][2 * nq],     ah[mi], bh[nq] + 0);
                    mma16816(acc[mi][2 * nq + 1], ah[mi], bh[nq] + 2);
                }
            // ---- term hl ----
            #pragma unroll
            for (int nq = 0; nq < 4; nq++)
                #pragma unroll
                for (int mi = 0; mi < 2; mi++) {
                    mma16816(acc[mi][2 * nq],     ah[mi], bl[nq] + 0);
                    mma16816(acc[mi][2 * nq + 1], ah[mi], bl[nq] + 2);
                }
            // ---- term lh ----
            #pragma unroll
            for (int nq = 0; nq < 4; nq++)
                #pragma unroll
                for (int mi = 0; mi < 2; mi++) {
                    mma16816(acc[mi][2 * nq],     al[mi], bh[nq] + 0);
                    mma16816(acc[mi][2 * nq + 1], al[mi], bh[nq] + 2);
                }
        }
        __syncthreads();
        if (it + 2 < NIT) { load_stage(s, (it + 2) * KC); cpa_commit(); }
    }

    const int g = lane >> 2, tg = lane & 3;
    #pragma unroll
    for (int mi = 0; mi < 2; mi++) {
        #pragma unroll
        for (int nf = 0; nf < 8; nf++) {
            const int col = bcol + wn + nf * 8 + 2 * tg;
            const float b0 = bias[col], b1 = bias[col + 1];
            #pragma unroll
            for (int half = 0; half < 2; half++) {
                const int row = brow + wm + 16 * mi + g + 8 * half;
                const float v0 = (acc[mi][nf][2 * half + 0] + b0) * scale;
                const float v1 = (acc[mi][nf][2 * half + 1] + b1) * scale;
                if (MODE == 0) {
                    *(float2*)(Cf + (size_t)row * DM + col) = make_float2(v0, v1);
                } else {
                    const int bb = row >> 11, sq = row & (SEQ - 1);
                    const int hh = col >> 6,  dd = col & (HD - 1);
                    const size_t idx = (((size_t)(bb * NH + hh) * SEQ + sq) * HD + dd);
                    unsigned hi, lo;
                    splitpack(v0, v1, hi, lo);
                    *(unsigned*)(Chi + idx) = hi;
                    *(unsigned*)(Clo + idx) = lo;
                }
            }
        }
    }
}

// ============================================================================
// Flash attention (UNCHANGED from round-5 passing version)
// ============================================================================
#define QST 72
#define Q_PL   (128*QST)
#define KV_PL  (64*QST)
#define KV_STG (4*KV_PL)
#define KV_BASE (2*Q_PL)
#define ATTN_SMEM ((2*Q_PL + 2*KV_STG)*2)   // 110592 bytes

__global__ void __launch_bounds__(128, 2) mma_attn(
    const __nv_bfloat16* __restrict__ Qh, const __nv_bfloat16* __restrict__ Ql,
    const __nv_bfloat16* __restrict__ Kh, const __nv_bfloat16* __restrict__ Kl,
    const __nv_bfloat16* __restrict__ Vh, const __nv_bfloat16* __restrict__ Vl,
    __nv_bfloat16* __restrict__ Ohi, __nv_bfloat16* __restrict__ Olo)
{
    extern __shared__ ushort_t sm[];

    const int tid = threadIdx.x, lane = tid & 31, warp = tid >> 5;
    const int q0 = blockIdx.x * 128;
    const int h  = blockIdx.y,  b = blockIdx.z;
    const size_t hoff = (size_t)(b * NH + h) * SEQ * HD;

    const __nv_bfloat16* kvp[4] = { Kh + hoff, Kl + hoff, Vh + hoff, Vl + hoff };

    const int lr = tid >> 3, lc = (tid & 7) * 8;

    auto load_kv = [&](int stage, int kv0) {
        #pragma unroll
        for (int k = 0; k < 16; k++) {
            const int p   = k >> 2;
            const int row = lr + (k & 3) * 16;
            cpa16(&sm[KV_BASE + stage * KV_STG + p * KV_PL + row * QST + lc],
                  kvp[p] + (size_t)(kv0 + row) * HD + lc);
        }
    };

    {
        const __nv_bfloat16* qp[2] = { Qh + hoff, Ql + hoff };
        #pragma unroll
        for (int k = 0; k < 16; k++) {
            const int p   = k >> 3;
            const int row = lr + (k & 7) * 16;
            cpa16(&sm[p * Q_PL + row * QST + lc],
                  qp[p] + (size_t)(q0 + row) * HD + lc);
        }
    }
    load_kv(0, 0); cpa_commit();
    load_kv(1, 64); cpa_commit();

    const int g = lane >> 2, tg = lane & 3;
    float m[2][2], l[2][2], o[2][8][4];
    #pragma unroll
    for (int mi = 0; mi < 2; mi++) {
        m[mi][0] = -INFINITY; m[mi][1] = -INFINITY;
        l[mi][0] = 0.f;       l[mi][1] = 0.f;
        #pragma unroll
        for (int i = 0; i < 8; i++)
            #pragma unroll
            for (int c = 0; c < 4; c++) o[mi][i][c] = 0.f;
    }

    const int NIT = SEQ / 64;   // 32
    for (int it = 0; it < NIT; it++) {
        if (it < NIT - 1) cpa_wait<1>(); else cpa_wait<0>();
        __syncthreads();

        const int stage = it & 1;
        ushort_t* Ksh = sm + KV_BASE + stage * KV_STG;
        ushort_t* Ksl = Ksh + KV_PL;
        ushort_t* Vsh = Ksl + KV_PL;
        ushort_t* Vsl = Vsh + KV_PL;

        float s[2][8][4];
        #pragma unroll
        for (int mi = 0; mi < 2; mi++)
            #pragma unroll
            for (int i = 0; i < 8; i++)
                #pragma unroll
                for (int c = 0; c < 4; c++) s[mi][i][c] = 0.f;

        #pragma unroll
        for (int ks = 0; ks < 4; ks++) {
            unsigned ah[2][4], al[2][4];
            #pragma unroll
            for (int mi = 0; mi < 2; mi++) {
                const int ar = warp * 32 + 16 * mi + (lane & 15);
                const int ac = ks * 16 + ((lane & 16) ? 8 : 0);
                ldsm4(ah[mi], &sm[0 * Q_PL + ar * QST + ac]);
                ldsm4(al[mi], &sm[1 * Q_PL + ar * QST + ac]);
            }
            #pragma unroll
            for (int nq = 0; nq < 4; nq++) {
                const int srow = nq * 16 + (lane & 7) + ((lane & 16) ? 8 : 0);
                const int dcol = ks * 16 + ((lane & 8) ? 8 : 0);
                unsigned bh[4], bl[4];
                ldsm4(bh, &Ksh[srow * QST + dcol]);
                ldsm4(bl, &Ksl[srow * QST + dcol]);
                #pragma unroll
                for (int mi = 0; mi < 2; mi++) {
                    mma16816(s[mi][2 * nq],     ah[mi], bh + 0);
                    mma16816(s[mi][2 * nq + 1], ah[mi], bh + 2);
                    mma16816(s[mi][2 * nq],     ah[mi], bl + 0);
                    mma16816(s[mi][2 * nq + 1], ah[mi], bl + 2);
                    mma16816(s[mi][2 * nq],     al[mi], bh + 0);
                    mma16816(s[mi][2 * nq + 1], al[mi], bh + 2);
                }
            }
        }

        unsigned ph[2][8][2], pl[2][8][2];
        #pragma unroll
        for (int mi = 0; mi < 2; mi++) {
            float mx0 = -INFINITY, mx1 = -INFINITY;
            #pragma unroll
            for (int i = 0; i < 8; i++) {
                mx0 = fmaxf(mx0, fmaxf(s[mi][i][0], s[mi][i][1]));
                mx1 = fmaxf(mx1, fmaxf(s[mi][i][2], s[mi][i][3]));
            }
            mx0 = fmaxf(mx0, __shfl_xor_sync(0xffffffffu, mx0, 1));
            mx0 = fmaxf(mx0, __shfl_xor_sync(0xffffffffu, mx0, 2));
            mx1 = fmaxf(mx1, __shfl_xor_sync(0xffffffffu, mx1, 1));
            mx1 = fmaxf(mx1, __shfl_xor_sync(0xffffffffu, mx1, 2));
            const float mn0 = fmaxf(m[mi][0], mx0), mn1 = fmaxf(m[mi][1], mx1);
            const float c0 = __expf(m[mi][0] - mn0), c1 = __expf(m[mi][1] - mn1);
            m[mi][0] = mn0; m[mi][1] = mn1;
            float rs0 = 0.f, rs1 = 0.f;
            #pragma unroll
            for (int i = 0; i < 8; i++) {
                s[mi][i][0] = __expf(s[mi][i][0] - mn0);
                s[mi][i][1] = __expf(s[mi][i][1] - mn0);
                s[mi][i][2] = __expf(s[mi][i][2] - mn1);
                s[mi][i][3] = __expf(s[mi][i][3] - mn1);
                rs0 += s[mi][i][0] + s[mi][i][1];
                rs1 += s[mi][i][2] + s[mi][i][3];
            }
            rs0 += __shfl_xor_sync(0xffffffffu, rs0, 1);
            rs0 += __shfl_xor_sync(0xffffffffu, rs0, 2);
            rs1 += __shfl_xor_sync(0xffffffffu, rs1, 1);
            rs1 += __shfl_xor_sync(0xffffffffu, rs1, 2);
            l[mi][0] = l[mi][0] * c0 + rs0;
            l[mi][1] = l[mi][1] * c1 + rs1;
            #pragma unroll
            for (int i = 0; i < 8; i++) {
                o[mi][i][0] *= c0; o[mi][i][1] *= c0;
                o[mi][i][2] *= c1; o[mi][i][3] *= c1;
                splitpack(s[mi][i][0], s[mi][i][1], ph[mi][i][0], pl[mi][i][0]);
                splitpack(s[mi][i][2], s[mi][i][3], ph[mi][i][1], pl[mi][i][1]);
            }
        }

        #pragma unroll
        for (int kss = 0; kss < 4; kss++) {
            unsigned a2h[2][4], a2l[2][4];
            #pragma unroll
            for (int mi = 0; mi < 2; mi++) {
                a2h[mi][0] = ph[mi][2 * kss][0];     a2h[mi][1] = ph[mi][2 * kss][1];
                a2h[mi][2] = ph[mi][2 * kss + 1][0]; a2h[mi][3] = ph[mi][2 * kss + 1][1];
                a2l[mi][0] = pl[mi][2 * kss][0];     a2l[mi][1] = pl[mi][2 * kss][1];
                a2l[mi][2] = pl[mi][2 * kss + 1][0]; a2l[mi][3] = pl[mi][2 * kss + 1][1];
            }
            #pragma unroll
            for (int nq = 0; nq < 4; nq++) {
                const int srow = kss * 16 + (lane & 7) + ((lane & 8) ? 8 : 0);
                const int dcol = nq * 16 + ((lane & 16) ? 8 : 0);
                unsigned bh[4], bl[4];
                ldsm4t(bh, &Vsh[srow * QST + dcol]);
                ldsm4t(bl, &Vsl[srow * QST + dcol]);
                #pragma unroll
                for (int mi = 0; mi < 2; mi++) {
                    mma16816(o[mi][2 * nq],     a2h[mi], bh + 0);
                    mma16816(o[mi][2 * nq + 1], a2h[mi], bh + 2);
                    mma16816(o[mi][2 * nq],     a2h[mi], bl + 0);
                    mma16816(o[mi][2 * nq + 1], a2h[mi], bl + 2);
                    mma16816(o[mi][2 * nq],     a2l[mi], bh + 0);
                    mma16816(o[mi][2 * nq + 1], a2l[mi], bh + 2);
                }
            }
        }
        __syncthreads();
        if (it + 2 < NIT) { load_kv(stage, (it + 2) * 64); cpa_commit(); }
    }

    #pragma unroll
    for (int mi = 0; mi < 2; mi++) {
        const float i0 = 1.f / l[mi][0], i1 = 1.f / l[mi][1];
        #pragma unroll
        for (int nf = 0; nf < 8; nf++) {
            const int d  = h * HD + nf * 8 + 2 * tg;
            const int r0 = q0 + warp * 32 + 16 * mi + g;
            unsigned hi, lo;
            splitpack(o[mi][nf][0] * i0, o[mi][nf][1] * i0, hi, lo);
            *(unsigned*)(Ohi + (size_t)(b * SEQ + r0) * DM + d) = hi;
            *(unsigned*)(Olo + (size_t)(b * SEQ + r0) * DM + d) = lo;
            splitpack(o[mi][nf][2] * i1, o[mi][nf][3] * i1, hi, lo);
            *(unsigned*)(Ohi + (size_t)(b * SEQ + r0 + 8) * DM + d) = hi;
            *(unsigned*)(Olo + (size_t)(b * SEQ + r0 + 8) * DM + d) = lo;
        }
    }
}

// ============================================================================
// launch
// ============================================================================
extern "C" void kernel_launch(void* const* d_in, const int* in_sizes, int n_in,
                              void* d_out, int out_size)
{
    const float* x  = (const float*)d_in[0];
    const float* Wq = (const float*)d_in[1];
    const float* bq = (const float*)d_in[2];
    const float* Wk = (const float*)d_in[3];
    const float* bk = (const float*)d_in[4];
    const float* Wv = (const float*)d_in[5];
    const float* bv = (const float*)d_in[6];
    const float* Wo = (const float*)d_in[7];
    const float* bo = (const float*)d_in[8];
    float* out = (float*)d_out;

    void *xh, *xl, *wqh, *wql, *wkh, *wkl, *wvh, *wvl, *woh, *wol;
    void *qh, *ql, *kh, *kl, *vh, *vl, *oh, *ol;
    cudaGetSymbolAddress(&xh, g_xh);   cudaGetSymbolAddress(&xl, g_xl);
    cudaGetSymbolAddress(&wqh, g_wqh); cudaGetSymbolAddress(&wql, g_wql);
    cudaGetSymbolAddress(&wkh, g_wkh); cudaGetSymbolAddress(&wkl, g_wkl);
    cudaGetSymbolAddress(&wvh, g_wvh); cudaGetSymbolAddress(&wvl, g_wvl);
    cudaGetSymbolAddress(&woh, g_woh); cudaGetSymbolAddress(&wol, g_wol);
    cudaGetSymbolAddress(&qh, g_qh);   cudaGetSymbolAddress(&ql, g_ql);
    cudaGetSymbolAddress(&kh, g_kh);   cudaGetSymbolAddress(&kl, g_kl);
    cudaGetSymbolAddress(&vh, g_vh);   cudaGetSymbolAddress(&vl, g_vl);
    cudaGetSymbolAddress(&oh, g_oh);   cudaGetSymbolAddress(&ol, g_ol);

    // prep: split x (row-major) + transpose-split the four weights to [N,K]
    split_kernel<<<512, 256>>>((const float2*)x, (unsigned*)xh, (unsigned*)xl, MTOT*DM/2);
    dim3 tb(32, 8), tg2(DM / 32, DM / 32);
    tsplit_kernel<<<tg2, tb>>>(Wq, (__nv_bfloat16*)wqh, (__nv_bfloat16*)wql);
    tsplit_kernel<<<tg2, tb>>>(Wk, (__nv_bfloat16*)wkh, (__nv_bfloat16*)wkl);
    tsplit_kernel<<<tg2, tb>>>(Wv, (__nv_bfloat16*)wvh, (__nv_bfloat16*)wvl);
    tsplit_kernel<<<tg2, tb>>>(Wo, (__nv_bfloat16*)woh, (__nv_bfloat16*)wol);

    cudaFuncSetAttribute(mma_gemm<0>, cudaFuncAttributeMaxDynamicSharedMemorySize, GEMM_SMEM);
    cudaFuncSetAttribute(mma_gemm<1>, cudaFuncAttributeMaxDynamicSharedMemorySize, GEMM_SMEM);
    cudaFuncSetAttribute(mma_attn, cudaFuncAttributeMaxDynamicSharedMemorySize, ATTN_SMEM);

    dim3 gg(DM / 128, MTOT / 128);   // (8, 32)
    mma_gemm<1><<<gg, 256, GEMM_SMEM>>>(
        (const __nv_bfloat16*)xh, (const __nv_bfloat16*)xl,
        (const __nv_bfloat16*)wqh, (const __nv_bfloat16*)wql,
        bq, 0.125f, nullptr, (__nv_bfloat16*)qh, (__nv_bfloat16*)ql);
    mma_gemm<1><<<gg, 256, GEMM_SMEM>>>(
        (const __nv_bfloat16*)xh, (const __nv_bfloat16*)xl,
        (const __nv_bfloat16*)wkh, (const __nv_bfloat16*)wkl,
        bk, 1.f, nullptr, (__nv_bfloat16*)kh, (__nv_bfloat16*)kl);
    mma_gemm<1><<<gg, 256, GEMM_SMEM>>>(
        (const __nv_bfloat16*)xh, (const __nv_bfloat16*)xl,
        (const __nv_bfloat16*)wvh, (const __nv_bfloat16*)wvl,
        bv, 1.f, nullptr, (__nv_bfloat16*)vh, (__nv_bfloat16*)vl);

    mma_attn<<<dim3(SEQ / 128, NH, BATCH), 128, ATTN_SMEM>>>(
        (const __nv_bfloat16*)qh, (const __nv_bfloat16*)ql,
        (const __nv_bfloat16*)kh, (const __nv_bfloat16*)kl,
        (const __nv_bfloat16*)vh, (const __nv_bfloat16*)vl,
        (__nv_bfloat16*)oh, (__nv_bfloat16*)ol);

    mma_gemm<0><<<gg, 256, GEMM_SMEM>>>(
        (const __nv_bfloat16*)oh, (const __nv_bfloat16*)ol,
        (const __nv_bfloat16*)woh, (const __nv_bfloat16*)wol,
        bo, 1.f, out, nullptr, nullptr);
}

// round 12
// speedup vs baseline: 1.5464x; 1.0027x over previous
#include <cuda_runtime.h>
#include <cuda_bf16.h>
#include <math.h>
#include <stdint.h>

#define BATCH 2
#define SEQ   2048
#define DM    1024
#define NH    16
#define HD    64
#define MTOT  (BATCH*SEQ)   // 4096

typedef unsigned short ushort_t;

// ---------------- scratch (__device__ globals; no cudaMalloc allowed) -------
__device__ __nv_bfloat16 g_xh[(size_t)MTOT*DM];   // x  [M,K] hi/lo
__device__ __nv_bfloat16 g_xl[(size_t)MTOT*DM];
__device__ __nv_bfloat16 g_wqh[(size_t)DM*DM];    // W^T [N,K] hi/lo
__device__ __nv_bfloat16 g_wql[(size_t)DM*DM];
__device__ __nv_bfloat16 g_wkh[(size_t)DM*DM];
__device__ __nv_bfloat16 g_wkl[(size_t)DM*DM];
__device__ __nv_bfloat16 g_wvh[(size_t)DM*DM];
__device__ __nv_bfloat16 g_wvl[(size_t)DM*DM];
__device__ __nv_bfloat16 g_woh[(size_t)DM*DM];
__device__ __nv_bfloat16 g_wol[(size_t)DM*DM];
__device__ __nv_bfloat16 g_qh[(size_t)MTOT*DM];   // [B,H,S,64]
__device__ __nv_bfloat16 g_ql[(size_t)MTOT*DM];
__device__ __nv_bfloat16 g_kh[(size_t)MTOT*DM];
__device__ __nv_bfloat16 g_kl[(size_t)MTOT*DM];
__device__ __nv_bfloat16 g_vh[(size_t)MTOT*DM];
__device__ __nv_bfloat16 g_vl[(size_t)MTOT*DM];
__device__ __nv_bfloat16 g_oh[(size_t)MTOT*DM];   // attn out [B,S,D]
__device__ __nv_bfloat16 g_ol[(size_t)MTOT*DM];

// ---------------- helpers ---------------------------------------------------
__device__ __forceinline__ void splitpack(float x, float y,
                                          unsigned &hi, unsigned &lo) {
    __nv_bfloat16 hx = __float2bfloat16(x);
    __nv_bfloat16 hy = __float2bfloat16(y);
    float lx = x - __bfloat162float(hx);
    float ly = y - __bfloat162float(hy);
    hi = ((unsigned)__bfloat16_as_ushort(hy) << 16) |
          (unsigned)__bfloat16_as_ushort(hx);
    lo = ((unsigned)__bfloat16_as_ushort(__float2bfloat16(ly)) << 16) |
          (unsigned)__bfloat16_as_ushort(__float2bfloat16(lx));
}
__device__ __forceinline__ void ldsm4(unsigned* r, const void* p) {
    unsigned a = (unsigned)__cvta_generic_to_shared(p);
    asm volatile("ldmatrix.sync.aligned.m8n8.x4.shared.b16 {%0,%1,%2,%3}, [%4];"
                 : "=r"(r[0]), "=r"(r[1]), "=r"(r[2]), "=r"(r[3]) : "r"(a));
}
__device__ __forceinline__ void ldsm4t(unsigned* r, const void* p) {
    unsigned a = (unsigned)__cvta_generic_to_shared(p);
    asm volatile("ldmatrix.sync.aligned.m8n8.x4.trans.shared.b16 {%0,%1,%2,%3}, [%4];"
                 : "=r"(r[0]), "=r"(r[1]), "=r"(r[2]), "=r"(r[3]) : "r"(a));
}
__device__ __forceinline__ void mma16816(float* c, const unsigned* a,
                                         const unsigned* b) {
    asm volatile(
        "mma.sync.aligned.m16n8k16.row.col.f32.bf16.bf16.f32 "
        "{%0,%1,%2,%3},{%4,%5,%6,%7},{%8,%9},{%0,%1,%2,%3};"
        : "+f"(c[0]), "+f"(c[1]), "+f"(c[2]), "+f"(c[3])
        : "r"(a[0]), "r"(a[1]), "r"(a[2]), "r"(a[3]), "r"(b[0]), "r"(b[1]));
}
__device__ __forceinline__ void cpa16(void* dst, const void* src) {
    unsigned d = (unsigned)__cvta_generic_to_shared(dst);
    asm volatile("cp.async.cg.shared.global [%0], [%1], 16;" :: "r"(d), "l"(src));
}
__device__ __forceinline__ void cpa_commit() {
    asm volatile("cp.async.commit_group;");
}
template <int N> __device__ __forceinline__ void cpa_wait() {
    asm volatile("cp.async.wait_group %0;" :: "n"(N));
}

// ============================================================================
// prep kernels
// ============================================================================
__global__ void split_kernel(const float2* __restrict__ src,
                             unsigned* __restrict__ hi,
                             unsigned* __restrict__ lo, int n2)
{
    for (int i = blockIdx.x * blockDim.x + threadIdx.x; i < n2;
         i += gridDim.x * blockDim.x) {
        float2 v = src[i];
        unsigned h, l;
        splitpack(v.x, v.y, h, l);
        hi[i] = h;
        lo[i] = l;
    }
}

// transpose + split: T[n,k] = W[k,n], hi/lo bf16 planes
__global__ void tsplit_kernel(const float* __restrict__ W,
                              __nv_bfloat16* __restrict__ Th,
                              __nv_bfloat16* __restrict__ Tl)
{
    __shared__ float t[32][33];
    const int n0 = blockIdx.x * 32, k0 = blockIdx.y * 32;
    const int tx = threadIdx.x, ty = threadIdx.y;
    #pragma unroll
    for (int i = 0; i < 4; i++)
        t[ty + 8 * i][tx] = W[(size_t)(k0 + ty + 8 * i) * DM + n0 + tx];
    __syncthreads();
    #pragma unroll
    for (int i = 0; i < 4; i++) {
        const float v = t[tx][ty + 8 * i];       // = W[k0+tx][n0+ty+8i]
        const __nv_bfloat16 h = __float2bfloat16(v);
        const size_t idx = (size_t)(n0 + ty + 8 * i) * DM + k0 + tx;
        Th[idx] = h;
        Tl[idx] = __float2bfloat16(v - __bfloat162float(h));
    }
}

// ============================================================================
// Split-bf16 GEMM v4: C[M,N] = A[M,K] @ B^T + bias, B stored [N,K] K-major.
// CTA tile 256x128x32, 256 thr, 8 warps (4m x 2n), warp tile 64x64.
// Per k-slice: 16 ldsm4 feed 96 MMAs (85 B/MMA, vs 128 in v3) AND
// distance-32 issue order (32x hh, 32x hl, 32x lh) so 2 warps/SMSP suffice.
// MODE 0: fp32 row-major out. MODE 1: bf16 hi/lo [B,H,S,64] out, scaled.
// ============================================================================
#define KC  32
#define PST 40                    // padded stride, halves (80 B)
#define APL (256*PST)             // A plane: 10240 halves
#define BPL (128*PST)             // B plane: 5120 halves
#define STG (2*APL + 2*BPL)       // 30720 halves per stage
#define GEMM_SMEM (2*STG*2)       // 122880 bytes

template <int MODE>
__global__ void __launch_bounds__(256, 1) mma_gemm(
    const __nv_bfloat16* __restrict__ Ah, const __nv_bfloat16* __restrict__ Al,
    const __nv_bfloat16* __restrict__ Bh, const __nv_bfloat16* __restrict__ Bl,
    const float* __restrict__ bias, float scale,
    float* __restrict__ Cf,
    __nv_bfloat16* __restrict__ Chi, __nv_bfloat16* __restrict__ Clo)
{
    extern __shared__ ushort_t gsm[];

    const int tid  = threadIdx.x;
    const int lane = tid & 31, warp = tid >> 5;        // 8 warps
    const int wm = (warp >> 1) * 64, wn = (warp & 1) * 64;
    const int brow = blockIdx.y * 256, bcol = blockIdx.x * 128;

    // 3072 cpa16 per stage, 12 per thread (it<8 -> A, it>=8 -> B)
    auto load_stage = [&](int s, int kt) {
        #pragma unroll
        for (int it = 0; it < 12; it++) {
            const int idx = tid + it * 256;
            if (idx < 2048) {                         // A planes
                const int p = idx >> 10;              // 0..1
                const int r = (idx >> 2) & 255;
                const int c = idx & 3;
                cpa16(&gsm[s * STG + p * APL + r * PST + c * 8],
                      (p ? Al : Ah) + (size_t)(brow + r) * DM + kt + c * 8);
            } else {                                  // B planes
                const int j = idx - 2048;
                const int p = j >> 9;                 // 0..1
                const int r = (j >> 2) & 127;
                const int c = j & 3;
                cpa16(&gsm[s * STG + 2 * APL + p * BPL + r * PST + c * 8],
                      (p ? Bl : Bh) + (size_t)(bcol + r) * DM + kt + c * 8);
            }
        }
    };

    float acc[4][8][4];
    #pragma unroll
    for (int i = 0; i < 4; i++)
        #pragma unroll
        for (int j = 0; j < 8; j++)
            #pragma unroll
            for (int c = 0; c < 4; c++) acc[i][j][c] = 0.f;

    load_stage(0, 0);  cpa_commit();
    load_stage(1, KC); cpa_commit();

    const int NIT = DM / KC;   // 32
    for (int it = 0; it < NIT; it++) {
        if (it < NIT - 1) cpa_wait<1>(); else cpa_wait<0>();
        __syncthreads();

        const int s = it & 1;
        ushort_t* A0 = gsm + s * STG;
        ushort_t* A1 = A0 + APL;
        ushort_t* B0 = A1 + APL;
        ushort_t* B1 = B0 + BPL;

        #pragma unroll
        for (int ks = 0; ks < 2; ks++) {
            // ---- load ALL fragments for this k-slice (16 ldsm4) ----
            unsigned ah[4][4], al[4][4], bh[4][4], bl[4][4];
            const int ac = ks * 16 + ((lane & 16) ? 8 : 0);
            #pragma unroll
            for (int mi = 0; mi < 4; mi++) {
                const int ar = wm + 16 * mi + (lane & 15);
                ldsm4(ah[mi], &A0[ar * PST + ac]);
                ldsm4(al[mi], &A1[ar * PST + ac]);
            }
            const int bc = ks * 16 + ((lane & 8) ? 8 : 0);
            #pragma unroll
            for (int nq = 0; nq < 4; nq++) {
                const int br = wn + nq * 16 + (lane & 7) + ((lane & 16) ? 8 : 0);
                ldsm4(bh[nq], &B0[br * PST + bc]);
                ldsm4(bl[nq], &B1[br * PST + bc]);
            }
            // ---- term hh: 32 MMAs, every acc touched once ----
            #pragma unroll
            for (int nq = 0; nq < 4; nq++)
                #pragma unroll
                for (int mi = 0; mi < 4; mi++) {
                    mma16816(acc[mi][2 * nq],     ah[mi], bh[nq] + 0);
                    mma16816(acc[mi][2 * nq + 1], ah[mi], bh[nq] + 2);
                }
            // ---- term hl ----
            #pragma unroll
            for (int nq = 0; nq < 4; nq++)
                #pragma unroll
                for (int mi = 0; mi < 4; mi++) {
                    mma16816(acc[mi][2 * nq],     ah[mi], bl[nq] + 0);
                    mma16816(acc[mi][2 * nq + 1], ah[mi], bl[nq] + 2);
                }
            // ---- term lh ----
            #pragma unroll
            for (int nq = 0; nq < 4; nq++)
                #pragma unroll
                for (int mi = 0; mi < 4; mi++) {
                    mma16816(acc[mi][2 * nq],     al[mi], bh[nq] + 0);
                    mma16816(acc[mi][2 * nq + 1], al[mi], bh[nq] + 2);
                }
        }
        __syncthreads();
        if (it + 2 < NIT) { load_stage(s, (it + 2) * KC); cpa_commit(); }
    }

    const int g = lane >> 2, tg = lane & 3;
    #pragma unroll
    for (int mi = 0; mi < 4; mi++) {
        #pragma unroll
        for (int nf = 0; nf < 8; nf++) {
            const int col = bcol + wn + nf * 8 + 2 * tg;
            const float b0 = bias[col], b1 = bias[col + 1];
            #pragma unroll
            for (int half = 0; half < 2; half++) {
                const int row = brow + wm + 16 * mi + g + 8 * half;
                const float v0 = (acc[mi][nf][2 * half + 0] + b0) * scale;
                const float v1 = (acc[mi][nf][2 * half + 1] + b1) * scale;
                if (MODE == 0) {
                    *(float2*)(Cf + (size_t)row * DM + col) = make_float2(v0, v1);
                } else {
                    const int bb = row >> 11, sq = row & (SEQ - 1);
                    const int hh = col >> 6,  dd = col & (HD - 1);
                    const size_t idx = (((size_t)(bb * NH + hh) * SEQ + sq) * HD + dd);
                    unsigned hi, lo;
                    splitpack(v0, v1, hi, lo);
                    *(unsigned*)(Chi + idx) = hi;
                    *(unsigned*)(Clo + idx) = lo;
                }
            }
        }
    }
}

// ============================================================================
// Flash attention (UNCHANGED from round-5 passing version)
// ============================================================================
#define QST 72
#define Q_PL   (128*QST)
#define KV_PL  (64*QST)
#define KV_STG (4*KV_PL)
#define KV_BASE (2*Q_PL)
#define ATTN_SMEM ((2*Q_PL + 2*KV_STG)*2)   // 110592 bytes

__global__ void __launch_bounds__(128, 2) mma_attn(
    const __nv_bfloat16* __restrict__ Qh, const __nv_bfloat16* __restrict__ Ql,
    const __nv_bfloat16* __restrict__ Kh, const __nv_bfloat16* __restrict__ Kl,
    const __nv_bfloat16* __restrict__ Vh, const __nv_bfloat16* __restrict__ Vl,
    __nv_bfloat16* __restrict__ Ohi, __nv_bfloat16* __restrict__ Olo)
{
    extern __shared__ ushort_t sm[];

    const int tid = threadIdx.x, lane = tid & 31, warp = tid >> 5;
    const int q0 = blockIdx.x * 128;
    const int h  = blockIdx.y,  b = blockIdx.z;
    const size_t hoff = (size_t)(b * NH + h) * SEQ * HD;

    const __nv_bfloat16* kvp[4] = { Kh + hoff, Kl + hoff, Vh + hoff, Vl + hoff };

    const int lr = tid >> 3, lc = (tid & 7) * 8;

    auto load_kv = [&](int stage, int kv0) {
        #pragma unroll
        for (int k = 0; k < 16; k++) {
            const int p   = k >> 2;
            const int row = lr + (k & 3) * 16;
            cpa16(&sm[KV_BASE + stage * KV_STG + p * KV_PL + row * QST + lc],
                  kvp[p] + (size_t)(kv0 + row) * HD + lc);
        }
    };

    {
        const __nv_bfloat16* qp[2] = { Qh + hoff, Ql + hoff };
        #pragma unroll
        for (int k = 0; k < 16; k++) {
            const int p   = k >> 3;
            const int row = lr + (k & 7) * 16;
            cpa16(&sm[p * Q_PL + row * QST + lc],
                  qp[p] + (size_t)(q0 + row) * HD + lc);
        }
    }
    load_kv(0, 0); cpa_commit();
    load_kv(1, 64); cpa_commit();

    const int g = lane >> 2, tg = lane & 3;
    float m[2][2], l[2][2], o[2][8][4];
    #pragma unroll
    for (int mi = 0; mi < 2; mi++) {
        m[mi][0] = -INFINITY; m[mi][1] = -INFINITY;
        l[mi][0] = 0.f;       l[mi][1] = 0.f;
        #pragma unroll
        for (int i = 0; i < 8; i++)
            #pragma unroll
            for (int c = 0; c < 4; c++) o[mi][i][c] = 0.f;
    }

    const int NIT = SEQ / 64;   // 32
    for (int it = 0; it < NIT; it++) {
        if (it < NIT - 1) cpa_wait<1>(); else cpa_wait<0>();
        __syncthreads();

        const int stage = it & 1;
        ushort_t* Ksh = sm + KV_BASE + stage * KV_STG;
        ushort_t* Ksl = Ksh + KV_PL;
        ushort_t* Vsh = Ksl + KV_PL;
        ushort_t* Vsl = Vsh + KV_PL;

        float s[2][8][4];
        #pragma unroll
        for (int mi = 0; mi < 2; mi++)
            #pragma unroll
            for (int i = 0; i < 8; i++)
                #pragma unroll
                for (int c = 0; c < 4; c++) s[mi][i][c] = 0.f;

        #pragma unroll
        for (int ks = 0; ks < 4; ks++) {
            unsigned ah[2][4], al[2][4];
            #pragma unroll
            for (int mi = 0; mi < 2; mi++) {
                const int ar = warp * 32 + 16 * mi + (lane & 15);
                const int ac = ks * 16 + ((lane & 16) ? 8 : 0);
                ldsm4(ah[mi], &sm[0 * Q_PL + ar * QST + ac]);
                ldsm4(al[mi], &sm[1 * Q_PL + ar * QST + ac]);
            }
            #pragma unroll
            for (int nq = 0; nq < 4; nq++) {
                const int srow = nq * 16 + (lane & 7) + ((lane & 16) ? 8 : 0);
                const int dcol = ks * 16 + ((lane & 8) ? 8 : 0);
                unsigned bh[4], bl[4];
                ldsm4(bh, &Ksh[srow * QST + dcol]);
                ldsm4(bl, &Ksl[srow * QST + dcol]);
                #pragma unroll
                for (int mi = 0; mi < 2; mi++) {
                    mma16816(s[mi][2 * nq],     ah[mi], bh + 0);
                    mma16816(s[mi][2 * nq + 1], ah[mi], bh + 2);
                    mma16816(s[mi][2 * nq],     ah[mi], bl + 0);
                    mma16816(s[mi][2 * nq + 1], ah[mi], bl + 2);
                    mma16816(s[mi][2 * nq],     al[mi], bh + 0);
                    mma16816(s[mi][2 * nq + 1], al[mi], bh + 2);
                }
            }
        }

        unsigned ph[2][8][2], pl[2][8][2];
        #pragma unroll
        for (int mi = 0; mi < 2; mi++) {
            float mx0 = -INFINITY, mx1 = -INFINITY;
            #pragma unroll
            for (int i = 0; i < 8; i++) {
                mx0 = fmaxf(mx0, fmaxf(s[mi][i][0], s[mi][i][1]));
                mx1 = fmaxf(mx1, fmaxf(s[mi][i][2], s[mi][i][3]));
            }
            mx0 = fmaxf(mx0, __shfl_xor_sync(0xffffffffu, mx0, 1));
            mx0 = fmaxf(mx0, __shfl_xor_sync(0xffffffffu, mx0, 2));
            mx1 = fmaxf(mx1, __shfl_xor_sync(0xffffffffu, mx1, 1));
            mx1 = fmaxf(mx1, __shfl_xor_sync(0xffffffffu, mx1, 2));
            const float mn0 = fmaxf(m[mi][0], mx0), mn1 = fmaxf(m[mi][1], mx1);
            const float c0 = __expf(m[mi][0] - mn0), c1 = __expf(m[mi][1] - mn1);
            m[mi][0] = mn0; m[mi][1] = mn1;
            float rs0 = 0.f, rs1 = 0.f;
            #pragma unroll
            for (int i = 0; i < 8; i++) {
                s[mi][i][0] = __expf(s[mi][i][0] - mn0);
                s[mi][i][1] = __expf(s[mi][i][1] - mn0);
                s[mi][i][2] = __expf(s[mi][i][2] - mn1);
                s[mi][i][3] = __expf(s[mi][i][3] - mn1);
                rs0 += s[mi][i][0] + s[mi][i][1];
                rs1 += s[mi][i][2] + s[mi][i][3];
            }
            rs0 += __shfl_xor_sync(0xffffffffu, rs0, 1);
            rs0 += __shfl_xor_sync(0xffffffffu, rs0, 2);
            rs1 += __shfl_xor_sync(0xffffffffu, rs1, 1);
            rs1 += __shfl_xor_sync(0xffffffffu, rs1, 2);
            l[mi][0] = l[mi][0] * c0 + rs0;
            l[mi][1] = l[mi][1] * c1 + rs1;
            #pragma unroll
            for (int i = 0; i < 8; i++) {
                o[mi][i][0] *= c0; o[mi][i][1] *= c0;
                o[mi][i][2] *= c1; o[mi][i][3] *= c1;
                splitpack(s[mi][i][0], s[mi][i][1], ph[mi][i][0], pl[mi][i][0]);
                splitpack(s[mi][i][2], s[mi][i][3], ph[mi][i][1], pl[mi][i][1]);
            }
        }

        #pragma unroll
        for (int kss = 0; kss < 4; kss++) {
            unsigned a2h[2][4], a2l[2][4];
            #pragma unroll
            for (int mi = 0; mi < 2; mi++) {
                a2h[mi][0] = ph[mi][2 * kss][0];     a2h[mi][1] = ph[mi][2 * kss][1];
                a2h[mi][2] = ph[mi][2 * kss + 1][0]; a2h[mi][3] = ph[mi][2 * kss + 1][1];
                a2l[mi][0] = pl[mi][2 * kss][0];     a2l[mi][1] = pl[mi][2 * kss][1];
                a2l[mi][2] = pl[mi][2 * kss + 1][0]; a2l[mi][3] = pl[mi][2 * kss + 1][1];
            }
            #pragma unroll
            for (int nq = 0; nq < 4; nq++) {
                const int srow = kss * 16 + (lane & 7) + ((lane & 8) ? 8 : 0);
                const int dcol = nq * 16 + ((lane & 16) ? 8 : 0);
                unsigned bh[4], bl[4];
                ldsm4t(bh, &Vsh[srow * QST + dcol]);
                ldsm4t(bl, &Vsl[srow * QST + dcol]);
                #pragma unroll
                for (int mi = 0; mi < 2; mi++) {
                    mma16816(o[mi][2 * nq],     a2h[mi], bh + 0);
                    mma16816(o[mi][2 * nq + 1], a2h[mi], bh + 2);
                    mma16816(o[mi][2 * nq],     a2h[mi], bl + 0);
                    mma16816(o[mi][2 * nq + 1], a2h[mi], bl + 2);
                    mma16816(o[mi][2 * nq],     a2l[mi], bh + 0);
                    mma16816(o[mi][2 * nq + 1], a2l[mi], bh + 2);
                }
            }
        }
        __syncthreads();
        if (it + 2 < NIT) { load_kv(stage, (it + 2) * 64); cpa_commit(); }
    }

    #pragma unroll
    for (int mi = 0; mi < 2; mi++) {
        const float i0 = 1.f / l[mi][0], i1 = 1.f / l[mi][1];
        #pragma unroll
        for (int nf = 0; nf < 8; nf++) {
            const int d  = h * HD + nf * 8 + 2 * tg;
            const int r0 = q0 + warp * 32 + 16 * mi + g;
            unsigned hi, lo;
            splitpack(o[mi][nf][0] * i0, o[mi][nf][1] * i0, hi, lo);
            *(unsigned*)(Ohi + (size_t)(b * SEQ + r0) * DM + d) = hi;
            *(unsigned*)(Olo + (size_t)(b * SEQ + r0) * DM + d) = lo;
            splitpack(o[mi][nf][2] * i1, o[mi][nf][3] * i1, hi, lo);
            *(unsigned*)(Ohi + (size_t)(b * SEQ + r0 + 8) * DM + d) = hi;
            *(unsigned*)(Olo + (size_t)(b * SEQ + r0 + 8) * DM + d) = lo;
        }
    }
}

// ============================================================================
// launch
// ============================================================================
extern "C" void kernel_launch(void* const* d_in, const int* in_sizes, int n_in,
                              void* d_out, int out_size)
{
    const float* x  = (const float*)d_in[0];
    const float* Wq = (const float*)d_in[1];
    const float* bq = (const float*)d_in[2];
    const float* Wk = (const float*)d_in[3];
    const float* bk = (const float*)d_in[4];
    const float* Wv = (const float*)d_in[5];
    const float* bv = (const float*)d_in[6];
    const float* Wo = (const float*)d_in[7];
    const float* bo = (const float*)d_in[8];
    float* out = (float*)d_out;

    void *xh, *xl, *wqh, *wql, *wkh, *wkl, *wvh, *wvl, *woh, *wol;
    void *qh, *ql, *kh, *kl, *vh, *vl, *oh, *ol;
    cudaGetSymbolAddress(&xh, g_xh);   cudaGetSymbolAddress(&xl, g_xl);
    cudaGetSymbolAddress(&wqh, g_wqh); cudaGetSymbolAddress(&wql, g_wql);
    cudaGetSymbolAddress(&wkh, g_wkh); cudaGetSymbolAddress(&wkl, g_wkl);
    cudaGetSymbolAddress(&wvh, g_wvh); cudaGetSymbolAddress(&wvl, g_wvl);
    cudaGetSymbolAddress(&woh, g_woh); cudaGetSymbolAddress(&wol, g_wol);
    cudaGetSymbolAddress(&qh, g_qh);   cudaGetSymbolAddress(&ql, g_ql);
    cudaGetSymbolAddress(&kh, g_kh);   cudaGetSymbolAddress(&kl, g_kl);
    cudaGetSymbolAddress(&vh, g_vh);   cudaGetSymbolAddress(&vl, g_vl);
    cudaGetSymbolAddress(&oh, g_oh);   cudaGetSymbolAddress(&ol, g_ol);

    // prep: split x (row-major) + transpose-split the four weights to [N,K]
    split_kernel<<<512, 256>>>((const float2*)x, (unsigned*)xh, (unsigned*)xl, MTOT*DM/2);
    dim3 tb(32, 8), tg2(DM / 32, DM / 32);
    tsplit_kernel<<<tg2, tb>>>(Wq, (__nv_bfloat16*)wqh, (__nv_bfloat16*)wql);
    tsplit_kernel<<<tg2, tb>>>(Wk, (__nv_bfloat16*)wkh, (__nv_bfloat16*)wkl);
    tsplit_kernel<<<tg2, tb>>>(Wv, (__nv_bfloat16*)wvh, (__nv_bfloat16*)wvl);
    tsplit_kernel<<<tg2, tb>>>(Wo, (__nv_bfloat16*)woh, (__nv_bfloat16*)wol);

    cudaFuncSetAttribute(mma_gemm<0>, cudaFuncAttributeMaxDynamicSharedMemorySize, GEMM_SMEM);
    cudaFuncSetAttribute(mma_gemm<1>, cudaFuncAttributeMaxDynamicSharedMemorySize, GEMM_SMEM);
    cudaFuncSetAttribute(mma_attn, cudaFuncAttributeMaxDynamicSharedMemorySize, ATTN_SMEM);

    dim3 gg(DM / 128, MTOT / 256);   // (8, 16) = 128 CTAs
    mma_gemm<1><<<gg, 256, GEMM_SMEM>>>(
        (const __nv_bfloat16*)xh, (const __nv_bfloat16*)xl,
        (const __nv_bfloat16*)wqh, (const __nv_bfloat16*)wql,
        bq, 0.125f, nullptr, (__nv_bfloat16*)qh, (__nv_bfloat16*)ql);
    mma_gemm<1><<<gg, 256, GEMM_SMEM>>>(
        (const __nv_bfloat16*)xh, (const __nv_bfloat16*)xl,
        (const __nv_bfloat16*)wkh, (const __nv_bfloat16*)wkl,
        bk, 1.f, nullptr, (__nv_bfloat16*)kh, (__nv_bfloat16*)kl);
    mma_gemm<1><<<gg, 256, GEMM_SMEM>>>(
        (const __nv_bfloat16*)xh, (const __nv_bfloat16*)xl,
        (const __nv_bfloat16*)wvh, (const __nv_bfloat16*)wvl,
        bv, 1.f, nullptr, (__nv_bfloat16*)vh, (__nv_bfloat16*)vl);

    mma_attn<<<dim3(SEQ / 128, NH, BATCH), 128, ATTN_SMEM>>>(
        (const __nv_bfloat16*)qh, (const __nv_bfloat16*)ql,
        (const __nv_bfloat16*)kh, (const __nv_bfloat16*)kl,
        (const __nv_bfloat16*)vh, (const __nv_bfloat16*)vl,
        (__nv_bfloat16*)oh, (__nv_bfloat16*)ol);

    mma_gemm<0><<<gg, 256, GEMM_SMEM>>>(
        (const __nv_bfloat16*)oh, (const __nv_bfloat16*)ol,
        (const __nv_bfloat16*)woh, (const __nv_bfloat16*)wol,
        bo, 1.f, out, nullptr, nullptr);
}